// round 13
// baseline (speedup 1.0000x reference)
#include <cuda_runtime.h>
#include <cuda_fp16.h>

#define NN 100000
#define NE 1000000
#define D  64
#define NB 98   // ceil(NN/1024)

typedef unsigned long long ull;

#define ADDX2(d, a, b_) asm("add.rn.f32x2 %0, %1, %2;" : "=l"(d) : "l"(a), "l"(b_))

// ---- device scratch (static, no allocation; zero-initialized at load) ----
__device__ int     g_deg[NN];        // edge-count; re-zeroed each run by k_scan23
__device__ float   g_dinv[NN];
__device__ int     g_off[NN + 1];
__device__ int     g_bsum[NB];
__device__ int     g_ppos[NE];       // per-edge rank within its dst bucket
__device__ int     g_csr_src[NE];
__device__ float   g_u0[NN * D];     // fp32 intermediates
__device__ float   g_u1[NN * D];
__device__ __half  g_h2[NN * D];

// 1) histogram of in-degree over dst; record each edge's bucket rank
__global__ void k_hist(const int* __restrict__ dst) {
    int e = blockIdx.x * blockDim.x + threadIdx.x;
    if (e < NE) g_ppos[e] = atomicAdd(&g_deg[dst[e]], 1);
}

// 2) per-block exclusive scan of edge-counts; block sums; dinv = rsqrt(deg+1)
__global__ void k_scan1() {
    __shared__ int wsum[32];
    int i = blockIdx.x * 1024 + threadIdx.x;
    int lane = threadIdx.x & 31, wid = threadIdx.x >> 5;
    int v = (i < NN) ? g_deg[i] : 0;            // edges into i
    if (i < NN) g_dinv[i] = rsqrtf((float)(v + 1));
    int s = v;
    #pragma unroll
    for (int d = 1; d < 32; d <<= 1) {
        int t = __shfl_up_sync(0xffffffffu, s, d);
        if (lane >= d) s += t;
    }
    if (lane == 31) wsum[wid] = s;
    __syncthreads();
    if (wid == 0) {
        int ws = wsum[lane];
        #pragma unroll
        for (int d = 1; d < 32; d <<= 1) {
            int t = __shfl_up_sync(0xffffffffu, ws, d);
            if (lane >= d) ws += t;
        }
        wsum[lane] = ws;
    }
    __syncthreads();
    int ex = s - v + (wid ? wsum[wid - 1] : 0);
    if (i < NN) g_off[i] = ex;                  // block-local exclusive
    if (threadIdx.x == 1023) g_bsum[blockIdx.x] = ex + v;
}

// 3) per-block: add block offset (self-computed), re-zero g_deg, u0 = dinv.*x
__global__ void k_scan23(const float* __restrict__ x) {
    __shared__ int sh_bex;
    if (threadIdx.x < 32) {
        int v = 0;
        for (int j = threadIdx.x; j < blockIdx.x; j += 32) v += g_bsum[j];
        #pragma unroll
        for (int d = 16; d; d >>= 1) v += __shfl_down_sync(0xffffffffu, v, d);
        if (threadIdx.x == 0) sh_bex = v;
    }
    __syncthreads();
    int i = blockIdx.x * 1024 + threadIdx.x;
    if (i < NN) {
        g_off[i] += sh_bex;
        g_deg[i] = 0;                 // restore for next graph replay
    }
    if (i == 0) g_off[NN] = NE;
    // fused prep for this block's node range (float2 in -> float2 out)
    int base = blockIdx.x * 1024 * 32;          // element-pair index
    const float2* x2 = (const float2*)x;
    float2* u02 = (float2*)g_u0;
    #pragma unroll 4
    for (int t = threadIdx.x; t < 1024 * 32; t += 1024) {
        int idx = base + t;
        if (idx < NN * 32) {
            float di = g_dinv[idx >> 5];
            float2 v = __ldg(&x2[idx]);
            float2 o; o.x = di * v.x; o.y = di * v.y;
            u02[idx] = o;
        }
    }
}

// 4) scatter edge sources into CSR buckets by dst — NO atomics
__global__ void k_scatter(const int* __restrict__ src, const int* __restrict__ dst) {
    int e = blockIdx.x * blockDim.x + threadIdx.x;
    if (e < NE) {
        int d = dst[e];
        int p = __ldg(&g_off[d]) + g_ppos[e];
        g_csr_src[p] = src[e];
    }
}

// ---- hop: HALF-WARP per node; lane covers 4 floats via LDG.128 ----
// One warp instruction serves 2 edges (one per half-warp).
// PASS 0: in = g_u0, out = g_u1 (fp32), scale = dinv^2
// PASS 1: in = g_u1, out = g_h2 (fp16), scale = dinv
template <int PASS>
__global__ void k_hop() {
    const float* __restrict__ in =
        (PASS == 0) ? (const float*)g_u0 : (const float*)g_u1;

    int gw   = (blockIdx.x * blockDim.x + threadIdx.x) >> 5;   // warp id
    int lane = threadIdx.x & 31;
    int half = lane >> 4;            // 0 or 1
    int sub  = lane & 15;            // lane within half
    int node = gw * 2 + half;
    if (node >= NN) return;          // never taken (NN even, grid exact)

    // self term: 4 floats = 2 packed f32x2
    const ull* row = (const ull*)(in + node * D) + sub * 2;
    ull A0 = __ldg(&row[0]);
    ull A1 = __ldg(&row[1]);

    int beg = g_off[node], end = g_off[node + 1];
    int n = end - beg;               // my half's edge count
    int nOther = __shfl_xor_sync(0xffffffffu, n, 16);
    int nmax = n > nOther ? n : nOther;   // warp-uniform

    for (int cb = 0; cb < nmax; cb += 16) {
        int myS = (cb + sub < n) ? __ldg(&g_csr_src[beg + cb + sub]) : 0;
        int lim = nmax - cb; if (lim > 16) lim = 16;   // warp-uniform
        #pragma unroll 4
        for (int k = 0; k < lim; k++) {
            int s = __shfl_sync(0xffffffffu, myS, (lane & 16) + k);
            if (cb + k < n) {
                const ull* r = (const ull*)(in + s * D) + sub * 2;
                ull v0 = __ldg(&r[0]);
                ull v1 = __ldg(&r[1]);
                ADDX2(A0, A0, v0);
                ADDX2(A1, A1, v1);
            }
        }
    }

    float a0x, a0y, a1x, a1y;
    asm("mov.b64 {%0, %1}, %2;" : "=f"(a0x), "=f"(a0y) : "l"(A0));
    asm("mov.b64 {%0, %1}, %2;" : "=f"(a1x), "=f"(a1y) : "l"(A1));
    float di = g_dinv[node];
    if (PASS == 0) {
        float sc = di * di;
        float4 o; o.x = a0x * sc; o.y = a0y * sc; o.z = a1x * sc; o.w = a1y * sc;
        ((float4*)(g_u1 + node * D))[sub] = o;
    } else {
        float2 lo; lo.x = a0x * di; lo.y = a0y * di;
        float2 hi; hi.x = a1x * di; hi.y = a1y * di;
        __half2 hlo = __float22half2_rn(lo);
        __half2 hhi = __float22half2_rn(hi);
        ull packed;
        asm("mov.b64 %0, {%1, %2};" : "=l"(packed)
            : "r"(*(unsigned*)&hlo), "r"(*(unsigned*)&hhi));
        ((ull*)(g_h2 + node * D))[sub] = packed;
    }
}

// 5) out = g_h2 @ W^T + b  (packed fma.rn.f32x2: 2 cols x 4 rows per thread)
__global__ void k_lin(const float* __restrict__ W, const float* __restrict__ b,
                      float* __restrict__ out) {
    __shared__ ull Wp[D * 32];   // Wp[k*32+c2] = (W[2c2][k], W[2c2+1][k])
    __shared__ float hs[32 * D]; // 32 staged rows
    __shared__ ull bp[32];

    for (int t = threadIdx.x; t < D * 32; t += 256) {
        int k = t >> 5, c2 = t & 31;
        float lo = W[(2 * c2) * D + k];
        float hi = W[(2 * c2 + 1) * D + k];
        ull u;
        asm("mov.b64 %0, {%1, %2};" : "=l"(u) : "f"(lo), "f"(hi));
        Wp[t] = u;
    }
    if (threadIdx.x < 32) {
        ull u;
        asm("mov.b64 %0, {%1, %2};" : "=l"(u)
            : "f"(b[2 * threadIdx.x]), "f"(b[2 * threadIdx.x + 1]));
        bp[threadIdx.x] = u;
    }
    __syncthreads();

    int wid = threadIdx.x >> 5, lane = threadIdx.x & 31;

    for (int r0 = blockIdx.x * 32; r0 < NN; r0 += gridDim.x * 32) {
        const __half2* src = (const __half2*)g_h2 + r0 * 32;
        #pragma unroll
        for (int t = threadIdx.x; t < 1024; t += 256)
            ((float2*)hs)[t] = __half22float2(__ldg(&src[t]));
        __syncthreads();

        ull a0 = bp[lane], a1 = a0, a2 = a0, a3 = a0;
        const float* h0 = &hs[(wid * 4 + 0) * D];
        const float* h1 = &hs[(wid * 4 + 1) * D];
        const float* h2 = &hs[(wid * 4 + 2) * D];
        const float* h3 = &hs[(wid * 4 + 3) * D];
        #pragma unroll
        for (int k = 0; k < D; k++) {
            ull wv = Wp[k * 32 + lane];
            float v0 = h0[k], v1 = h1[k], v2 = h2[k], v3 = h3[k];
            ull p0, p1, p2, p3;
            asm("mov.b64 %0, {%1, %1};" : "=l"(p0) : "f"(v0));
            asm("mov.b64 %0, {%1, %1};" : "=l"(p1) : "f"(v1));
            asm("mov.b64 %0, {%1, %1};" : "=l"(p2) : "f"(v2));
            asm("mov.b64 %0, {%1, %1};" : "=l"(p3) : "f"(v3));
            asm("fma.rn.f32x2 %0, %1, %2, %3;" : "=l"(a0) : "l"(p0), "l"(wv), "l"(a0));
            asm("fma.rn.f32x2 %0, %1, %2, %3;" : "=l"(a1) : "l"(p1), "l"(wv), "l"(a1));
            asm("fma.rn.f32x2 %0, %1, %2, %3;" : "=l"(a2) : "l"(p2), "l"(wv), "l"(a2));
            asm("fma.rn.f32x2 %0, %1, %2, %3;" : "=l"(a3) : "l"(p3), "l"(wv), "l"(a3));
        }
        int r = r0 + wid * 4;
        ull* o = (ull*)out;
        o[(r + 0) * 32 + lane] = a0;
        o[(r + 1) * 32 + lane] = a1;
        o[(r + 2) * 32 + lane] = a2;
        o[(r + 3) * 32 + lane] = a3;
        __syncthreads();
    }
}

extern "C" void kernel_launch(void* const* d_in, const int* in_sizes, int n_in,
                              void* d_out, int out_size) {
    const float* x  = (const float*)d_in[0];                 // [NN, D]
    const int*   ei = (const int*)d_in[1];                   // [2, NE]
    const float* W  = (const float*)d_in[2];                 // [D, D]
    const float* b  = (const float*)d_in[3];                 // [D]
    const int* src = ei;
    const int* dst = ei + NE;
    float* out = (float*)d_out;

    // g_deg starts zeroed (static init) and is re-zeroed by k_scan23 each run.
    k_hist<<<(NE + 255) / 256, 256>>>(dst);
    k_scan1<<<NB, 1024>>>();
    k_scan23<<<NB, 1024>>>(x);
    k_scatter<<<(NE + 255) / 256, 256>>>(src, dst);
    // half-warp per node: NN/2 warps -> NN*16 threads
    k_hop<0><<<(NN * 16 + 255) / 256, 256>>>();
    k_hop<1><<<(NN * 16 + 255) / 256, 256>>>();
    k_lin<<<1184, 256>>>(W, b, out);
}

// round 14
// speedup vs baseline: 1.0662x; 1.0662x over previous
#include <cuda_runtime.h>
#include <cuda_fp16.h>

#define NN 100000
#define NE 1000000
#define D  64
#define NB 98   // ceil(NN/1024)

typedef unsigned long long ull;

// ---- device scratch (static, no allocation; zero-initialized at load) ----
__device__ int     g_deg[NN];        // edge-count; re-zeroed each run by k_scan23
__device__ float   g_dinv[NN];
__device__ int     g_off[NN + 1];
__device__ int     g_bsum[NB];
__device__ int     g_ppos[NE];       // per-edge rank within its dst bucket
__device__ int     g_csr_src[NE];
__device__ __half  g_u0[NN * D];     // fp16 intermediates
__device__ __half  g_u1[NN * D];
__device__ __half  g_h2[NN * D];

// 1) histogram of in-degree over dst; record each edge's bucket rank
__global__ void k_hist(const int* __restrict__ dst) {
    int e = blockIdx.x * blockDim.x + threadIdx.x;
    if (e < NE) g_ppos[e] = atomicAdd(&g_deg[dst[e]], 1);
}

// 2) per-block exclusive scan of edge-counts; block sums; dinv = rsqrt(deg+1)
__global__ void k_scan1() {
    __shared__ int wsum[32];
    int i = blockIdx.x * 1024 + threadIdx.x;
    int lane = threadIdx.x & 31, wid = threadIdx.x >> 5;
    int v = (i < NN) ? g_deg[i] : 0;            // edges into i
    if (i < NN) g_dinv[i] = rsqrtf((float)(v + 1));
    int s = v;
    #pragma unroll
    for (int d = 1; d < 32; d <<= 1) {
        int t = __shfl_up_sync(0xffffffffu, s, d);
        if (lane >= d) s += t;
    }
    if (lane == 31) wsum[wid] = s;
    __syncthreads();
    if (wid == 0) {
        int ws = wsum[lane];
        #pragma unroll
        for (int d = 1; d < 32; d <<= 1) {
            int t = __shfl_up_sync(0xffffffffu, ws, d);
            if (lane >= d) ws += t;
        }
        wsum[lane] = ws;
    }
    __syncthreads();
    int ex = s - v + (wid ? wsum[wid - 1] : 0);
    if (i < NN) g_off[i] = ex;                  // block-local exclusive
    if (threadIdx.x == 1023) g_bsum[blockIdx.x] = ex + v;
}

// 3) per-block: add block offset (self-computed), re-zero g_deg, u0 = fp16(dinv.*x)
__global__ void k_scan23(const float* __restrict__ x) {
    __shared__ int sh_bex;
    if (threadIdx.x < 32) {
        int v = 0;
        for (int j = threadIdx.x; j < blockIdx.x; j += 32) v += g_bsum[j];
        #pragma unroll
        for (int d = 16; d; d >>= 1) v += __shfl_down_sync(0xffffffffu, v, d);
        if (threadIdx.x == 0) sh_bex = v;
    }
    __syncthreads();
    int i = blockIdx.x * 1024 + threadIdx.x;
    if (i < NN) {
        g_off[i] += sh_bex;
        g_deg[i] = 0;                 // restore for next graph replay
    }
    if (i == 0) g_off[NN] = NE;
    // fused prep for this block's node range (float2 in -> half2 out)
    int base = blockIdx.x * 1024 * 32;          // element-pair index
    const float2* x2 = (const float2*)x;
    __half2* u02 = (__half2*)g_u0;
    #pragma unroll 4
    for (int t = threadIdx.x; t < 1024 * 32; t += 1024) {
        int idx = base + t;
        if (idx < NN * 32) {
            float di = g_dinv[idx >> 5];
            float2 v = __ldg(&x2[idx]);
            float2 o; o.x = di * v.x; o.y = di * v.y;
            u02[idx] = __float22half2_rn(o);
        }
    }
}

// 4) scatter edge sources into CSR buckets by dst — NO atomics
__global__ void k_scatter(const int* __restrict__ src, const int* __restrict__ dst) {
    int e = blockIdx.x * blockDim.x + threadIdx.x;
    if (e < NE) {
        int d = dst[e];
        int p = __ldg(&g_off[d]) + g_ppos[e];
        g_csr_src[p] = src[e];
    }
}

// ---- hop: warp per node, fp16 gather with pairwise HADD2 pre-reduction ----
// Per edge-pair: 2 SHFL + 2 LDG + 1 HADD2 + 2 F2F + 2 FADD  (~5.5 instr/edge)
// PASS 0: in = g_u0 (fp16), out = g_u1 (fp16), scale = dinv^2
// PASS 1: in = g_u1 (fp16), out = g_h2 (fp16), scale = dinv
template <int PASS>
__global__ void k_hop() {
    const __half2* __restrict__ in2 =
        (PASS == 0) ? (const __half2*)g_u0 : (const __half2*)g_u1;

    int gw   = (blockIdx.x * blockDim.x + threadIdx.x) >> 5;
    int lane = threadIdx.x & 31;
    if (gw >= NN) return;
    const int i = gw;
    float2 acc = __half22float2(__ldg(&in2[i * 32 + lane]));   // self term
    int beg = g_off[i], end = g_off[i + 1];
    for (int c = beg; c < end; c += 32) {
        int n = end - c; if (n > 32) n = 32;
        int myS = (c + lane < end) ? __ldg(&g_csr_src[c + lane]) : 0;
        int k = 0;
        for (; k + 8 <= n; k += 8) {
            int s0 = __shfl_sync(0xffffffffu, myS, k + 0);
            int s1 = __shfl_sync(0xffffffffu, myS, k + 1);
            int s2 = __shfl_sync(0xffffffffu, myS, k + 2);
            int s3 = __shfl_sync(0xffffffffu, myS, k + 3);
            int s4 = __shfl_sync(0xffffffffu, myS, k + 4);
            int s5 = __shfl_sync(0xffffffffu, myS, k + 5);
            int s6 = __shfl_sync(0xffffffffu, myS, k + 6);
            int s7 = __shfl_sync(0xffffffffu, myS, k + 7);
            __half2 v0 = __ldg(&in2[s0 * 32 + lane]);
            __half2 v1 = __ldg(&in2[s1 * 32 + lane]);
            __half2 v2 = __ldg(&in2[s2 * 32 + lane]);
            __half2 v3 = __ldg(&in2[s3 * 32 + lane]);
            __half2 v4 = __ldg(&in2[s4 * 32 + lane]);
            __half2 v5 = __ldg(&in2[s5 * 32 + lane]);
            __half2 v6 = __ldg(&in2[s6 * 32 + lane]);
            __half2 v7 = __ldg(&in2[s7 * 32 + lane]);
            __half2 p0 = __hadd2(v0, v1);
            __half2 p1 = __hadd2(v2, v3);
            __half2 p2 = __hadd2(v4, v5);
            __half2 p3 = __hadd2(v6, v7);
            float2 f0 = __half22float2(p0);
            float2 f1 = __half22float2(p1);
            float2 f2 = __half22float2(p2);
            float2 f3 = __half22float2(p3);
            acc.x += f0.x; acc.y += f0.y;
            acc.x += f1.x; acc.y += f1.y;
            acc.x += f2.x; acc.y += f2.y;
            acc.x += f3.x; acc.y += f3.y;
        }
        for (; k + 2 <= n; k += 2) {
            int s0 = __shfl_sync(0xffffffffu, myS, k + 0);
            int s1 = __shfl_sync(0xffffffffu, myS, k + 1);
            __half2 v0 = __ldg(&in2[s0 * 32 + lane]);
            __half2 v1 = __ldg(&in2[s1 * 32 + lane]);
            float2 f = __half22float2(__hadd2(v0, v1));
            acc.x += f.x; acc.y += f.y;
        }
        if (k < n) {
            int s = __shfl_sync(0xffffffffu, myS, k);
            float2 f = __half22float2(__ldg(&in2[s * 32 + lane]));
            acc.x += f.x; acc.y += f.y;
        }
    }
    float di = g_dinv[i];
    if (PASS == 0) {
        float sc = di * di;
        acc.x *= sc; acc.y *= sc;
        ((__half2*)g_u1)[i * 32 + lane] = __float22half2_rn(acc);
    } else {
        acc.x *= di; acc.y *= di;
        ((__half2*)g_h2)[i * 32 + lane] = __float22half2_rn(acc);
    }
}

// 5) out = g_h2 @ W^T + b  (packed fma.rn.f32x2: 2 cols x 4 rows per thread)
__global__ void k_lin(const float* __restrict__ W, const float* __restrict__ b,
                      float* __restrict__ out) {
    __shared__ ull Wp[D * 32];   // Wp[k*32+c2] = (W[2c2][k], W[2c2+1][k])
    __shared__ float hs[32 * D]; // 32 staged rows
    __shared__ ull bp[32];

    for (int t = threadIdx.x; t < D * 32; t += 256) {
        int k = t >> 5, c2 = t & 31;
        float lo = W[(2 * c2) * D + k];
        float hi = W[(2 * c2 + 1) * D + k];
        ull u;
        asm("mov.b64 %0, {%1, %2};" : "=l"(u) : "f"(lo), "f"(hi));
        Wp[t] = u;
    }
    if (threadIdx.x < 32) {
        ull u;
        asm("mov.b64 %0, {%1, %2};" : "=l"(u)
            : "f"(b[2 * threadIdx.x]), "f"(b[2 * threadIdx.x + 1]));
        bp[threadIdx.x] = u;
    }
    __syncthreads();

    int wid = threadIdx.x >> 5, lane = threadIdx.x & 31;

    for (int r0 = blockIdx.x * 32; r0 < NN; r0 += gridDim.x * 32) {
        const __half2* src = (const __half2*)g_h2 + r0 * 32;
        #pragma unroll
        for (int t = threadIdx.x; t < 1024; t += 256)
            ((float2*)hs)[t] = __half22float2(__ldg(&src[t]));
        __syncthreads();

        ull a0 = bp[lane], a1 = a0, a2 = a0, a3 = a0;
        const float* h0 = &hs[(wid * 4 + 0) * D];
        const float* h1 = &hs[(wid * 4 + 1) * D];
        const float* h2 = &hs[(wid * 4 + 2) * D];
        const float* h3 = &hs[(wid * 4 + 3) * D];
        #pragma unroll
        for (int k = 0; k < D; k++) {
            ull wv = Wp[k * 32 + lane];
            float v0 = h0[k], v1 = h1[k], v2 = h2[k], v3 = h3[k];
            ull p0, p1, p2, p3;
            asm("mov.b64 %0, {%1, %1};" : "=l"(p0) : "f"(v0));
            asm("mov.b64 %0, {%1, %1};" : "=l"(p1) : "f"(v1));
            asm("mov.b64 %0, {%1, %1};" : "=l"(p2) : "f"(v2));
            asm("mov.b64 %0, {%1, %1};" : "=l"(p3) : "f"(v3));
            asm("fma.rn.f32x2 %0, %1, %2, %3;" : "=l"(a0) : "l"(p0), "l"(wv), "l"(a0));
            asm("fma.rn.f32x2 %0, %1, %2, %3;" : "=l"(a1) : "l"(p1), "l"(wv), "l"(a1));
            asm("fma.rn.f32x2 %0, %1, %2, %3;" : "=l"(a2) : "l"(p2), "l"(wv), "l"(a2));
            asm("fma.rn.f32x2 %0, %1, %2, %3;" : "=l"(a3) : "l"(p3), "l"(wv), "l"(a3));
        }
        int r = r0 + wid * 4;
        ull* o = (ull*)out;
        o[(r + 0) * 32 + lane] = a0;
        o[(r + 1) * 32 + lane] = a1;
        o[(r + 2) * 32 + lane] = a2;
        o[(r + 3) * 32 + lane] = a3;
        __syncthreads();
    }
}

extern "C" void kernel_launch(void* const* d_in, const int* in_sizes, int n_in,
                              void* d_out, int out_size) {
    const float* x  = (const float*)d_in[0];                 // [NN, D]
    const int*   ei = (const int*)d_in[1];                   // [2, NE]
    const float* W  = (const float*)d_in[2];                 // [D, D]
    const float* b  = (const float*)d_in[3];                 // [D]
    const int* src = ei;
    const int* dst = ei + NE;
    float* out = (float*)d_out;

    // g_deg starts zeroed (static init) and is re-zeroed by k_scan23 each run.
    k_hist<<<(NE + 255) / 256, 256>>>(dst);
    k_scan1<<<NB, 1024>>>();
    k_scan23<<<NB, 1024>>>(x);
    k_scatter<<<(NE + 255) / 256, 256>>>(src, dst);
    k_hop<0><<<(NN * 32 + 255) / 256, 256>>>();
    k_hop<1><<<(NN * 32 + 255) / 256, 256>>>();
    k_lin<<<1184, 256>>>(W, b, out);
}

// round 15
// speedup vs baseline: 1.1050x; 1.0364x over previous
#include <cuda_runtime.h>
#include <cuda_fp16.h>

#define NN 100000
#define NE 1000000
#define D  64
#define NB 98   // ceil(NN/1024)

typedef unsigned long long ull;

// ---- device scratch (static, no allocation; zero-initialized at load) ----
__device__ int     g_deg[NN];        // edge-count; re-zeroed each run by k_scan23_off
__device__ float   g_dinv[NN];
__device__ int     g_off[NN + 1];
__device__ int     g_bsum[NB];
__device__ int     g_ppos[NE];       // per-edge rank within its dst bucket
__device__ int     g_csr_src[NE];
__device__ __half  g_u0[NN * D];     // fp16 intermediates
__device__ __half  g_u1[NN * D];
__device__ __half  g_h2[NN * D];

// 1) histogram of in-degree over dst; record each edge's bucket rank
__global__ void k_hist(const int* __restrict__ dst) {
    int e = blockIdx.x * blockDim.x + threadIdx.x;
    if (e < NE) g_ppos[e] = atomicAdd(&g_deg[dst[e]], 1);
}

// 2) per-block exclusive scan of edge-counts; block sums; dinv = rsqrt(deg+1)
__global__ void k_scan1() {
    __shared__ int wsum[32];
    int i = blockIdx.x * 1024 + threadIdx.x;
    int lane = threadIdx.x & 31, wid = threadIdx.x >> 5;
    int v = (i < NN) ? g_deg[i] : 0;            // edges into i
    if (i < NN) g_dinv[i] = rsqrtf((float)(v + 1));
    int s = v;
    #pragma unroll
    for (int d = 1; d < 32; d <<= 1) {
        int t = __shfl_up_sync(0xffffffffu, s, d);
        if (lane >= d) s += t;
    }
    if (lane == 31) wsum[wid] = s;
    __syncthreads();
    if (wid == 0) {
        int ws = wsum[lane];
        #pragma unroll
        for (int d = 1; d < 32; d <<= 1) {
            int t = __shfl_up_sync(0xffffffffu, ws, d);
            if (lane >= d) ws += t;
        }
        wsum[lane] = ws;
    }
    __syncthreads();
    int ex = s - v + (wid ? wsum[wid - 1] : 0);
    if (i < NN) g_off[i] = ex;                  // block-local exclusive
    if (threadIdx.x == 1023) g_bsum[blockIdx.x] = ex + v;
}

// 3a) per-block: add block offset (self-computed via bsum reduce), re-zero g_deg
__global__ void k_scan23_off() {
    __shared__ int sh_bex;
    if (threadIdx.x < 32) {
        int v = 0;
        for (int j = threadIdx.x; j < blockIdx.x; j += 32) v += g_bsum[j];
        #pragma unroll
        for (int d = 16; d; d >>= 1) v += __shfl_down_sync(0xffffffffu, v, d);
        if (threadIdx.x == 0) sh_bex = v;
    }
    __syncthreads();
    int i = blockIdx.x * 1024 + threadIdx.x;
    if (i < NN) {
        g_off[i] += sh_bex;
        g_deg[i] = 0;                 // restore for next graph replay
    }
    if (i == 0) g_off[NN] = NE;
}

// 3b) u0 = fp16(dinv .* x)   — depends only on scan1 (dinv); runs on side stream
__global__ void k_prep(const float* __restrict__ x) {
    int idx = blockIdx.x * blockDim.x + threadIdx.x;   // element-pair index
    if (idx < NN * 32) {
        float di = g_dinv[idx >> 5];
        float2 v = __ldg(&((const float2*)x)[idx]);
        float2 o; o.x = di * v.x; o.y = di * v.y;
        ((__half2*)g_u0)[idx] = __float22half2_rn(o);
    }
}

// 4) scatter edge sources into CSR buckets by dst — NO atomics
__global__ void k_scatter(const int* __restrict__ src, const int* __restrict__ dst) {
    int e = blockIdx.x * blockDim.x + threadIdx.x;
    if (e < NE) {
        int d = dst[e];
        int p = __ldg(&g_off[d]) + g_ppos[e];
        g_csr_src[p] = src[e];
    }
}

// ---- hop: warp per node, fp16 gather with pairwise HADD2 pre-reduction ----
// PASS 0: in = g_u0 (fp16), out = g_u1 (fp16), scale = dinv^2
// PASS 1: in = g_u1 (fp16), out = g_h2 (fp16), scale = dinv
template <int PASS>
__global__ void k_hop() {
    const __half2* __restrict__ in2 =
        (PASS == 0) ? (const __half2*)g_u0 : (const __half2*)g_u1;

    int gw   = (blockIdx.x * blockDim.x + threadIdx.x) >> 5;
    int lane = threadIdx.x & 31;
    if (gw >= NN) return;
    const int i = gw;
    float2 acc = __half22float2(__ldg(&in2[i * 32 + lane]));   // self term
    int beg = g_off[i], end = g_off[i + 1];
    for (int c = beg; c < end; c += 32) {
        int n = end - c; if (n > 32) n = 32;
        int myS = (c + lane < end) ? __ldg(&g_csr_src[c + lane]) : 0;
        int k = 0;
        for (; k + 8 <= n; k += 8) {
            int s0 = __shfl_sync(0xffffffffu, myS, k + 0);
            int s1 = __shfl_sync(0xffffffffu, myS, k + 1);
            int s2 = __shfl_sync(0xffffffffu, myS, k + 2);
            int s3 = __shfl_sync(0xffffffffu, myS, k + 3);
            int s4 = __shfl_sync(0xffffffffu, myS, k + 4);
            int s5 = __shfl_sync(0xffffffffu, myS, k + 5);
            int s6 = __shfl_sync(0xffffffffu, myS, k + 6);
            int s7 = __shfl_sync(0xffffffffu, myS, k + 7);
            __half2 v0 = __ldg(&in2[s0 * 32 + lane]);
            __half2 v1 = __ldg(&in2[s1 * 32 + lane]);
            __half2 v2 = __ldg(&in2[s2 * 32 + lane]);
            __half2 v3 = __ldg(&in2[s3 * 32 + lane]);
            __half2 v4 = __ldg(&in2[s4 * 32 + lane]);
            __half2 v5 = __ldg(&in2[s5 * 32 + lane]);
            __half2 v6 = __ldg(&in2[s6 * 32 + lane]);
            __half2 v7 = __ldg(&in2[s7 * 32 + lane]);
            __half2 p0 = __hadd2(v0, v1);
            __half2 p1 = __hadd2(v2, v3);
            __half2 p2 = __hadd2(v4, v5);
            __half2 p3 = __hadd2(v6, v7);
            float2 f0 = __half22float2(p0);
            float2 f1 = __half22float2(p1);
            float2 f2 = __half22float2(p2);
            float2 f3 = __half22float2(p3);
            acc.x += f0.x; acc.y += f0.y;
            acc.x += f1.x; acc.y += f1.y;
            acc.x += f2.x; acc.y += f2.y;
            acc.x += f3.x; acc.y += f3.y;
        }
        for (; k + 2 <= n; k += 2) {
            int s0 = __shfl_sync(0xffffffffu, myS, k + 0);
            int s1 = __shfl_sync(0xffffffffu, myS, k + 1);
            __half2 v0 = __ldg(&in2[s0 * 32 + lane]);
            __half2 v1 = __ldg(&in2[s1 * 32 + lane]);
            float2 f = __half22float2(__hadd2(v0, v1));
            acc.x += f.x; acc.y += f.y;
        }
        if (k < n) {
            int s = __shfl_sync(0xffffffffu, myS, k);
            float2 f = __half22float2(__ldg(&in2[s * 32 + lane]));
            acc.x += f.x; acc.y += f.y;
        }
    }
    float di = g_dinv[i];
    if (PASS == 0) {
        float sc = di * di;
        acc.x *= sc; acc.y *= sc;
        ((__half2*)g_u1)[i * 32 + lane] = __float22half2_rn(acc);
    } else {
        acc.x *= di; acc.y *= di;
        ((__half2*)g_h2)[i * 32 + lane] = __float22half2_rn(acc);
    }
}

// 5) out = g_h2 @ W^T + b  (packed fma.rn.f32x2: 2 cols x 4 rows per thread)
__global__ void k_lin(const float* __restrict__ W, const float* __restrict__ b,
                      float* __restrict__ out) {
    __shared__ ull Wp[D * 32];   // Wp[k*32+c2] = (W[2c2][k], W[2c2+1][k])
    __shared__ float hs[32 * D]; // 32 staged rows
    __shared__ ull bp[32];

    for (int t = threadIdx.x; t < D * 32; t += 256) {
        int k = t >> 5, c2 = t & 31;
        float lo = W[(2 * c2) * D + k];
        float hi = W[(2 * c2 + 1) * D + k];
        ull u;
        asm("mov.b64 %0, {%1, %2};" : "=l"(u) : "f"(lo), "f"(hi));
        Wp[t] = u;
    }
    if (threadIdx.x < 32) {
        ull u;
        asm("mov.b64 %0, {%1, %2};" : "=l"(u)
            : "f"(b[2 * threadIdx.x]), "f"(b[2 * threadIdx.x + 1]));
        bp[threadIdx.x] = u;
    }
    __syncthreads();

    int wid = threadIdx.x >> 5, lane = threadIdx.x & 31;

    for (int r0 = blockIdx.x * 32; r0 < NN; r0 += gridDim.x * 32) {
        const __half2* src = (const __half2*)g_h2 + r0 * 32;
        #pragma unroll
        for (int t = threadIdx.x; t < 1024; t += 256)
            ((float2*)hs)[t] = __half22float2(__ldg(&src[t]));
        __syncthreads();

        ull a0 = bp[lane], a1 = a0, a2 = a0, a3 = a0;
        const float* h0 = &hs[(wid * 4 + 0) * D];
        const float* h1 = &hs[(wid * 4 + 1) * D];
        const float* h2 = &hs[(wid * 4 + 2) * D];
        const float* h3 = &hs[(wid * 4 + 3) * D];
        #pragma unroll
        for (int k = 0; k < D; k++) {
            ull wv = Wp[k * 32 + lane];
            float v0 = h0[k], v1 = h1[k], v2 = h2[k], v3 = h3[k];
            ull p0, p1, p2, p3;
            asm("mov.b64 %0, {%1, %1};" : "=l"(p0) : "f"(v0));
            asm("mov.b64 %0, {%1, %1};" : "=l"(p1) : "f"(v1));
            asm("mov.b64 %0, {%1, %1};" : "=l"(p2) : "f"(v2));
            asm("mov.b64 %0, {%1, %1};" : "=l"(p3) : "f"(v3));
            asm("fma.rn.f32x2 %0, %1, %2, %3;" : "=l"(a0) : "l"(p0), "l"(wv), "l"(a0));
            asm("fma.rn.f32x2 %0, %1, %2, %3;" : "=l"(a1) : "l"(p1), "l"(wv), "l"(a1));
            asm("fma.rn.f32x2 %0, %1, %2, %3;" : "=l"(a2) : "l"(p2), "l"(wv), "l"(a2));
            asm("fma.rn.f32x2 %0, %1, %2, %3;" : "=l"(a3) : "l"(p3), "l"(wv), "l"(a3));
        }
        int r = r0 + wid * 4;
        ull* o = (ull*)out;
        o[(r + 0) * 32 + lane] = a0;
        o[(r + 1) * 32 + lane] = a1;
        o[(r + 2) * 32 + lane] = a2;
        o[(r + 3) * 32 + lane] = a3;
        __syncthreads();
    }
}

extern "C" void kernel_launch(void* const* d_in, const int* in_sizes, int n_in,
                              void* d_out, int out_size) {
    const float* x  = (const float*)d_in[0];                 // [NN, D]
    const int*   ei = (const int*)d_in[1];                   // [2, NE]
    const float* W  = (const float*)d_in[2];                 // [D, D]
    const float* b  = (const float*)d_in[3];                 // [D]
    const int* src = ei;
    const int* dst = ei + NE;
    float* out = (float*)d_out;

    // Side stream + events, created once on the first (non-capture) call.
    // Every call issues the IDENTICAL launch DAG; capture sees a static fork/join.
    static cudaStream_t s2 = nullptr;
    static cudaEvent_t ev1 = nullptr, ev2 = nullptr;
    if (!s2) {
        cudaStreamCreateWithFlags(&s2, cudaStreamNonBlocking);
        cudaEventCreateWithFlags(&ev1, cudaEventDisableTiming);
        cudaEventCreateWithFlags(&ev2, cudaEventDisableTiming);
    }

    k_hist<<<(NE + 255) / 256, 256>>>(dst);
    k_scan1<<<NB, 1024>>>();

    // fork: prep (needs only dinv) runs concurrent with offset-fixup + scatter
    cudaEventRecord(ev1, 0);
    cudaStreamWaitEvent(s2, ev1, 0);
    k_prep<<<(NN * 32 + 255) / 256, 256, 0, s2>>>(x);
    cudaEventRecord(ev2, s2);

    k_scan23_off<<<NB, 1024>>>();
    k_scatter<<<(NE + 255) / 256, 256>>>(src, dst);

    // join: hop0 needs both CSR (stream 0) and u0 (s2)
    cudaStreamWaitEvent(0, ev2, 0);
    k_hop<0><<<(NN * 32 + 255) / 256, 256>>>();
    k_hop<1><<<(NN * 32 + 255) / 256, 256>>>();
    k_lin<<<1184, 256>>>(W, b, out);
}